// round 13
// baseline (speedup 1.0000x reference)
#include <cuda_runtime.h>
#include <cuda_fp16.h>
#include <math.h>
#include <stdint.h>

#define BATCH 32
#define C     256
#define COUT  256
#define H     56
#define W     56
#define HW    3136

#define XWORDS 1856          // x tile: 232 pos x 8 words (word c = fp16 pair ci 2c,2c+1)
#define XPAD   2048
#define WWORDS 9216          // w buffer: 9 taps x 128 couts x 8 words
#define SMEM_WORDS (2 * XPAD + 2 * WWORDS)      // 22528
#define SMEM_BYTES (SMEM_WORDS * 4)             // 90112
#define NSLOT  16

// Packed quantized fp16 weights: [chunk(16)][tap(9)][cout(256)][slot(16)]
__device__ unsigned short g_wq[16u * 9u * 256u * 16u];

// floor-to-2^-16-grid then round-to-fp16 (round_to_fixed clamps dead: |x|<<32768)
__device__ __forceinline__ uint32_t quant_pack(float a, float b) {
    float fa = (float)__float2int_rd(a * 65536.0f) * (1.0f / 65536.0f);
    float fb = (float)__float2int_rd(b * 65536.0f) * (1.0f / 65536.0f);
    __half2 h = __floats2half2_rn(fa, fb);
    return *(uint32_t*)&h;
}
__device__ __forceinline__ float quant_scalar(float x) {
    return (float)__float2int_rd(x * 65536.0f) * (1.0f / 65536.0f);
}

__device__ __forceinline__ uint32_t smem_u32(const void* p) {
    uint32_t a;
    asm("{ .reg .u64 t; cvta.to.shared.u64 t, %1; cvt.u32.u64 %0, t; }" : "=r"(a) : "l"(p));
    return a;
}
#define CP_ASYNC16(dst, src) \
    asm volatile("cp.async.cg.shared.global [%0], [%1], 16;" :: "r"(dst), "l"(src))
#define CP_COMMIT()  asm volatile("cp.async.commit_group;" ::: "memory")
#define CP_WAIT0()   asm volatile("cp.async.wait_group 0;" ::: "memory")

// x smem addressing: pos p (0..231), word c (0..7).
// 16B chunk = 2p + (c>>2), XOR-swizzled: chunk ^= (chunk>>3)&1.
// word = (chunk<<2) | (c&3).  LDSM rows and STS groups both conflict-free.
__device__ __forceinline__ int x_word(int p, int c) {
    int ch = 2 * p + (c >> 2);
    ch ^= (ch >> 3) & 1;
    return (ch << 2) | (c & 3);
}

// ---------------- weight pre-quantization / packing ----------------
__global__ void quant_weights_kernel(const float* __restrict__ shiftp,
                                     const float* __restrict__ signp)
{
    int gid = blockIdx.x * blockDim.x + threadIdx.x;   // [cout][ci][tap]
    int cout = gid / (C * 9);
    int rem  = gid - cout * (C * 9);
    int ci   = rem / 9;
    int tap  = rem - ci * 9;

    float sr = rintf(fminf(fmaxf(shiftp[gid], -14.0f), 0.0f));
    float g  = rintf(signp[gid]);
    float sg = (g > 0.0f) ? 1.0f : ((g < 0.0f) ? -1.0f : 0.0f);
    float wf = ldexpf(sg, (int)sr);
    __half h = __float2half(wf);                       // exact

    int chunk = ci >> 4;
    int l     = ci & 15;
    int slot  = ((l >> 1) & 3) * 4 + (l >> 3) * 2 + (l & 1);
    g_wq[(((size_t)(chunk * 9 + tap) * 256 + cout) << 4) + slot] = __half_as_ushort(h);
}

// ---------------- main MMA conv ----------------
// CTA: M=112 (2 rows), N=128. 8 warps = 2(M) x 4(N).
// MTS=4 warps: pure cp.async+MMA. MTS=3 warps (128 thr) own all x staging.
// A fragments via ldmatrix.x4 from transposed+swizzled x tile (1 LDSM
// replaces 4 LDS.32). x/w double-buffered, one barrier/chunk, unroll-2.

template<int MTS, bool STAGE>
__device__ __forceinline__ void conv_body(
    const float* __restrict__ in_b,
    const float* __restrict__ biasp,
    float* __restrict__ out_b,
    uint32_t* __restrict__ smem,
    int oh_base, int cout0, int tid, int wn, int mt0)
{
    uint32_t* const sx0 = smem;
    uint32_t* const sx1 = smem + XPAD;
    uint32_t* const sw0 = smem + 2 * XPAD;
    uint32_t* const sw1 = smem + 2 * XPAD + WWORDS;
    const uint32_t sx0a = smem_u32(sx0), sx1a = smem_u32(sx1);
    const uint32_t sw0a = smem_u32(sw0), sw1a = smem_u32(sw1);

    const int lane = tid & 31;
    const int qc = lane & 3;
    const int qr = lane >> 2;

    // ldmatrix lane row geometry: chunk base = 2*pos(m) + (lane>>4)
    int cbase[MTS];
#pragma unroll
    for (int mt = 0; mt < MTS; ++mt) {
        int m = (mt0 + mt) * 16 + (lane & 15);
        int p = (m / 56) * 58 + (m % 56);
        cbase[mt] = 2 * p + (lane >> 4);
    }

    float acc[MTS][4][4];
#pragma unroll
    for (int mt = 0; mt < MTS; ++mt)
#pragma unroll
        for (int nn = 0; nn < 4; ++nn)
#pragma unroll
            for (int r = 0; r < 4; ++r) acc[mt][nn][r] = 0.0f;

    const char* wsrc_base = (const char*)g_wq + ((size_t)cout0 * 32);

    // ---- staging geometry: 16 slots (2 k-half groups x 8 iters of 128 thr) ----
    int xoff[STAGE ? NSLOT : 1];   // LDG offset, <0 = zero-fill
    int wadr[STAGE ? NSLOT : 1];   // STS word index, <0 = dead slot
    const int g = wn * 32 + lane;
    if (STAGE) {
#pragma unroll
        for (int sl = 0; sl < NSLOT; ++sl) {
            int h  = sl >> 3;
            int j2 = (sl & 7) * 128 + g;
            if (j2 < 928) {
                int pos = (j2 & 7) + ((j2 >> 5) << 3);
                int c   = h * 4 + ((j2 >> 3) & 3);
                int row = pos / 58, col = pos - row * 58;
                int ih = oh_base + row - 1, iw = col - 1;
                bool inb = (ih >= 0) && (ih < H) && (iw >= 0) && (iw < W);
                xoff[sl] = inb ? (2 * c * HW + ih * W + iw) : -1;
                wadr[sl] = x_word(pos, c);
            } else { xoff[sl] = -1; wadr[sl] = -1; }
        }
        // prologue x chunk 0
#pragma unroll
        for (int sl = 0; sl < NSLOT; ++sl) {
            if (wadr[sl] >= 0) {
                float v0 = 0.0f, v1 = 0.0f;
                if (xoff[sl] >= 0) {
                    const float* p = in_b + xoff[sl];
                    v0 = __ldg(p); v1 = __ldg(p + HW);
                }
                sx0[wadr[sl]] = quant_pack(v0, v1);
            }
        }
    }
#pragma unroll
    for (int tap = 0; tap < 9; ++tap)
        CP_ASYNC16(sw0a + tap * 4096 + tid * 16,
                   wsrc_base + (size_t)tap * 8192 + tid * 16);
    CP_COMMIT();

#pragma unroll 2
    for (int chunk = 0; chunk < 16; ++chunk) {
        const int cur = chunk & 1;                 // compile-time after unroll-2
        const uint32_t xca = cur ? sx1a : sx0a;
        uint32_t* const xn = cur ? sx0 : sx1;
        const uint32_t* wc = cur ? sw1 : sw0;
        const uint32_t wna = cur ? sw0a : sw1a;
        const bool hasnext = (chunk < 15);

        CP_WAIT0();
        __syncthreads();   // cur buffers ready; nxt buffers free

        float pv0[STAGE ? NSLOT : 1], pv1[STAGE ? NSLOT : 1];
        if (STAGE && hasnext) {
            const float* inc_n = in_b + (size_t)(chunk + 1) * 16 * HW;
#pragma unroll
            for (int sl = 0; sl < NSLOT; ++sl) {
                pv0[sl] = 0.0f; pv1[sl] = 0.0f;
                if (xoff[sl] >= 0) {
                    const float* p = inc_n + xoff[sl];
                    pv0[sl] = __ldg(p); pv1[sl] = __ldg(p + HW);
                }
            }
        }
        if (hasnext) {
            const char* wsrc = wsrc_base + (size_t)(chunk + 1) * 9 * 8192;
#pragma unroll
            for (int tap = 0; tap < 9; ++tap)
                CP_ASYNC16(wna + tap * 4096 + tid * 16,
                           wsrc + (size_t)tap * 8192 + tid * 16);
            CP_COMMIT();
        }

        // ---- pure MMA tap loop: 1 LDSM.x4 (A) + 4 LDS.64 (B) + 16 HMMA per mt ----
#pragma unroll
        for (int tap = 0; tap < 9; ++tap) {
            const int kh = tap / 3, kw = tap - kh * 3;
            const int ctap = 2 * (kh * 58 + kw);   // chunk delta for this tap

            uint32_t b0[4], b1[4];
#pragma unroll
            for (int nn = 0; nn < 4; ++nn) {
                int cl = wn * 32 + nn * 8 + qr;
                uint2 bb = *(const uint2*)&wc[tap * 1024 + cl * 8 + 2 * qc];
                b0[nn] = bb.x; b1[nn] = bb.y;
            }
#pragma unroll
            for (int mt = 0; mt < MTS; ++mt) {
                int ch = cbase[mt] + ctap;
                ch ^= (ch >> 3) & 1;
                uint32_t a0, a1, a2, a3;
                asm volatile(
                    "ldmatrix.sync.aligned.m8n8.x4.shared.b16 {%0,%1,%2,%3}, [%4];"
                    : "=r"(a0), "=r"(a1), "=r"(a2), "=r"(a3)
                    : "r"(xca + ((uint32_t)ch << 4)));
#pragma unroll
                for (int nn = 0; nn < 4; ++nn) {
                    asm volatile(
                        "mma.sync.aligned.m16n8k16.row.col.f32.f16.f16.f32 "
                        "{%0,%1,%2,%3}, {%4,%5,%6,%7}, {%8,%9}, {%0,%1,%2,%3};\n"
                        : "+f"(acc[mt][nn][0]), "+f"(acc[mt][nn][1]),
                          "+f"(acc[mt][nn][2]), "+f"(acc[mt][nn][3])
                        : "r"(a0), "r"(a1), "r"(a2), "r"(a3),
                          "r"(b0[nn]), "r"(b1[nn]));
                }
            }
        }

        // STS next x — hazards covered by next top barrier
        if (STAGE && hasnext) {
#pragma unroll
            for (int sl = 0; sl < NSLOT; ++sl)
                if (wadr[sl] >= 0)
                    xn[wadr[sl]] = quant_pack(pv0[sl], pv1[sl]);
        }
    }

    // ---- epilogue ----
#pragma unroll
    for (int nn = 0; nn < 4; ++nn) {
        int cl = wn * 32 + nn * 8 + 2 * qc;
        float bq0 = quant_scalar(biasp[cout0 + cl]);
        float bq1 = quant_scalar(biasp[cout0 + cl + 1]);
        float* o0 = out_b + (size_t)(cout0 + cl) * HW;
        float* o1 = o0 + HW;
#pragma unroll
        for (int mt = 0; mt < MTS; ++mt) {
            int mA = (mt0 + mt) * 16 + qr;
            int mB = mA + 8;
            int iA = (oh_base + mA / 56) * W + (mA % 56);
            int iB = (oh_base + mB / 56) * W + (mB % 56);
            o0[iA] = acc[mt][nn][0] + bq0;
            o1[iA] = acc[mt][nn][1] + bq1;
            o0[iB] = acc[mt][nn][2] + bq0;
            o1[iB] = acc[mt][nn][3] + bq1;
        }
    }
}

__global__ __launch_bounds__(256, 2)
void conv_mma_kernel(const float* __restrict__ in,
                     const float* __restrict__ biasp,
                     float* __restrict__ out)
{
    extern __shared__ uint32_t smem[];

    const int tid = threadIdx.x;
    const int w   = tid >> 5;
    const int wm  = w & 1;
    const int wn  = w >> 1;
    const int oh_base = blockIdx.x * 2;
    const int cout0   = blockIdx.y * 128;
    const int b       = blockIdx.z;

    const float* in_b  = in  + (size_t)b * C * HW;
    float*       out_b = out + (size_t)b * COUT * HW;

    if (wm == 0)
        conv_body<4, false>(in_b, biasp, out_b, smem, oh_base, cout0, tid, wn, 0);
    else
        conv_body<3, true >(in_b, biasp, out_b, smem, oh_base, cout0, tid, wn, 4);
}

extern "C" void kernel_launch(void* const* d_in, const int* in_sizes, int n_in,
                              void* d_out, int out_size)
{
    const float* in    = (const float*)d_in[0];
    const float* shift = (const float*)d_in[1];
    const float* sign  = (const float*)d_in[2];
    const float* bias  = (const float*)d_in[3];
    float* out = (float*)d_out;

    cudaFuncSetAttribute(conv_mma_kernel,
                         cudaFuncAttributeMaxDynamicSharedMemorySize, SMEM_BYTES);

    quant_weights_kernel<<<2304, 256>>>(shift, sign);
    dim3 grid(H / 2, COUT / 128, BATCH);               // 28 x 2 x 32
    conv_mma_kernel<<<grid, 256, SMEM_BYTES>>>(in, bias, out);
}

// round 14
// speedup vs baseline: 1.2681x; 1.2681x over previous
#include <cuda_runtime.h>
#include <cuda_fp16.h>
#include <math.h>
#include <stdint.h>

#define BATCH 32
#define C     256
#define COUT  256
#define H     56
#define W     56
#define HW    3136

#define XWORDS 1856          // live x words: 8 pair-planes x 4 rows x 58 cols (stride 232)
#define XPAD   2048
#define SMEM_WORDS (2 * XPAD)
#define SMEM_BYTES (SMEM_WORDS * 4)             // 16384

// Packed quantized fp16 weights: [chunk(16)][tap(9)][cout(256)][slot(16)]
// +4096 ushort pad (one tap block) so the tap+1 prefetch never reads OOB.
__device__ unsigned short g_wq[16u * 9u * 256u * 16u + 4096u];

// floor-to-2^-16-grid then round-to-fp16 (round_to_fixed clamps dead: |x|<<32768)
__device__ __forceinline__ uint32_t quant_pack(float a, float b) {
    float fa = (float)__float2int_rd(a * 65536.0f) * (1.0f / 65536.0f);
    float fb = (float)__float2int_rd(b * 65536.0f) * (1.0f / 65536.0f);
    __half2 h = __floats2half2_rn(fa, fb);
    return *(uint32_t*)&h;
}
__device__ __forceinline__ float quant_scalar(float x) {
    return (float)__float2int_rd(x * 65536.0f) * (1.0f / 65536.0f);
}

// ---------------- weight pre-quantization / packing ----------------
__global__ void quant_weights_kernel(const float* __restrict__ shiftp,
                                     const float* __restrict__ signp)
{
    int gid = blockIdx.x * blockDim.x + threadIdx.x;   // [cout][ci][tap]
    int cout = gid / (C * 9);
    int rem  = gid - cout * (C * 9);
    int ci   = rem / 9;
    int tap  = rem - ci * 9;

    float sr = rintf(fminf(fmaxf(shiftp[gid], -14.0f), 0.0f));
    float g  = rintf(signp[gid]);
    float sg = (g > 0.0f) ? 1.0f : ((g < 0.0f) ? -1.0f : 0.0f);
    float wf = ldexpf(sg, (int)sr);
    __half h = __float2half(wf);                       // exact

    int chunk = ci >> 4;
    int l     = ci & 15;
    int slot  = ((l >> 1) & 3) * 4 + (l >> 3) * 2 + (l & 1);
    g_wq[(((size_t)(chunk * 9 + tap) * 256 + cout) << 4) + slot] = __half_as_ushort(h);
}

// ---------------- main MMA conv ----------------
// CTA: M=112 (2 rows), N=128. 8 warps = 2(M) x 4(N).
// B fragments come straight from L2 via LDG.64, software-pipelined ONE TAP
// AHEAD in registers (per-warp tap wall ~450cyc >> 234cyc L2 latency).
// No weight smem at all. A fragments via scalar LDS from double-buffered x
// tile (R11-proven path). MTS=3 warps own all x staging; MTS=4 pure MMA.

template<int MTS, int NS>
__device__ __forceinline__ void conv_body(
    const float* __restrict__ in_b,
    const float* __restrict__ biasp,
    float* __restrict__ out_b,
    uint32_t* __restrict__ smem,
    int oh_base, int cout0, int tid, int wn, int mt0)
{
    uint32_t* const sx0 = smem;
    uint32_t* const sx1 = smem + XPAD;

    const int lane = tid & 31;
    const int qc = lane & 3;
    const int qr = lane >> 2;

    int offA[MTS], offB[MTS];
#pragma unroll
    for (int mt = 0; mt < MTS; ++mt) {
        int mA = (mt0 + mt) * 16 + qr;
        int mB = mA + 8;
        offA[mt] = (mA / 56) * 58 + (mA % 56);
        offB[mt] = (mB / 56) * 58 + (mB % 56);
    }

    float acc[MTS][4][4];
#pragma unroll
    for (int mt = 0; mt < MTS; ++mt)
#pragma unroll
        for (int nn = 0; nn < 4; ++nn)
#pragma unroll
            for (int r = 0; r < 4; ++r) acc[mt][nn][r] = 0.0f;

    const int qc232 = qc * 232;

    // per-lane byte offsets into a tap block (8192 B = 256 couts x 32 B)
    const char* wptr = (const char*)g_wq;
    int loff[4];
#pragma unroll
    for (int nn = 0; nn < 4; ++nn)
        loff[nn] = (cout0 + wn * 32 + nn * 8 + qr) * 32 + qc * 8;

    // ---- staging geometry: NS slots per thread, stride 128 (wm=1 group only) ----
    int  xoff[NS > 0 ? NS : 1];
    bool xval[NS > 0 ? NS : 1];
    const int sbase = wn * 32 + lane;
    if (NS > 0) {
#pragma unroll
        for (int it = 0; it < NS; ++it) {
            int idx  = sbase + it * 128;
            int c    = idx / 232;
            int rem  = idx - c * 232;
            int row  = rem / 58;
            int col  = rem - row * 58;
            int ih   = oh_base + row - 1;
            int iw   = col - 1;
            xval[it] = (idx < XWORDS) && (ih >= 0) && (ih < H) && (iw >= 0) && (iw < W);
            xoff[it] = 2 * c * HW + ih * W + iw;
        }
        // prologue: stage x chunk 0 into sx0
#pragma unroll
        for (int it = 0; it < NS; ++it) {
            int idx = sbase + it * 128;
            if (idx < XWORDS) {
                float v0 = 0.0f, v1 = 0.0f;
                if (xval[it]) {
                    const float* p = in_b + xoff[it];
                    v0 = __ldg(p); v1 = __ldg(p + HW);
                }
                sx0[idx] = quant_pack(v0, v1);
            }
        }
    }

    // ---- prologue B: load (chunk0, tap0) fragments into cur regs ----
    uint2 bc[4];
#pragma unroll
    for (int nn = 0; nn < 4; ++nn)
        bc[nn] = __ldg((const uint2*)(wptr + loff[nn]));

#pragma unroll 2
    for (int chunk = 0; chunk < 16; ++chunk) {
        const int cur = chunk & 1;                 // compile-time after unroll-2
        uint32_t* const xc = cur ? sx1 : sx0;
        uint32_t* const xn = cur ? sx0 : sx1;
        const bool hasnext = (chunk < 15);

        __syncthreads();   // xc ready; xn free

        // front-batched x prefetch for chunk+1 (staging warps)
        float pv0[NS > 0 ? NS : 1], pv1[NS > 0 ? NS : 1];
        if (NS > 0 && hasnext) {
            const float* inc_n = in_b + (size_t)(chunk + 1) * 16 * HW;
#pragma unroll
            for (int it = 0; it < NS; ++it) {
                pv0[it] = 0.0f; pv1[it] = 0.0f;
                if (xval[it]) {
                    const float* p = inc_n + xoff[it];
                    pv0[it] = __ldg(p); pv1[it] = __ldg(p + HW);
                }
            }
        }

        // ---- MMA tap loop with 1-tap-ahead B register pipeline ----
#pragma unroll
        for (int tap = 0; tap < 9; ++tap) {
            // prefetch B for next tap (pad block makes the last one safe)
            const char* nptr = wptr + 8192;
            uint2 bn[4];
#pragma unroll
            for (int nn = 0; nn < 4; ++nn)
                bn[nn] = __ldg((const uint2*)(nptr + loff[nn]));

            const int kh = tap / 3, kw = tap - kh * 3;
            const int tadd = kh * 58 + kw;
#pragma unroll
            for (int mt = 0; mt < MTS; ++mt) {
                uint32_t a0 = xc[qc232 + tadd + offA[mt]];
                uint32_t a1 = xc[qc232 + tadd + offB[mt]];
                uint32_t a2 = xc[qc232 + 928 + tadd + offA[mt]];
                uint32_t a3 = xc[qc232 + 928 + tadd + offB[mt]];
#pragma unroll
                for (int nn = 0; nn < 4; ++nn) {
                    asm volatile(
                        "mma.sync.aligned.m16n8k16.row.col.f32.f16.f16.f32 "
                        "{%0,%1,%2,%3}, {%4,%5,%6,%7}, {%8,%9}, {%0,%1,%2,%3};\n"
                        : "+f"(acc[mt][nn][0]), "+f"(acc[mt][nn][1]),
                          "+f"(acc[mt][nn][2]), "+f"(acc[mt][nn][3])
                        : "r"(a0), "r"(a1), "r"(a2), "r"(a3),
                          "r"(bc[nn].x), "r"(bc[nn].y));
                }
            }
#pragma unroll
            for (int nn = 0; nn < 4; ++nn) bc[nn] = bn[nn];
            wptr = nptr;
        }

        // STS next x — hazards covered by next top barrier
        if (NS > 0 && hasnext) {
#pragma unroll
            for (int it = 0; it < NS; ++it) {
                int idx = sbase + it * 128;
                if (idx < XWORDS)
                    xn[idx] = quant_pack(pv0[it], pv1[it]);
            }
        }
    }

    // ---- epilogue ----
#pragma unroll
    for (int nn = 0; nn < 4; ++nn) {
        int cl = wn * 32 + nn * 8 + 2 * qc;
        float bq0 = quant_scalar(biasp[cout0 + cl]);
        float bq1 = quant_scalar(biasp[cout0 + cl + 1]);
        float* o0 = out_b + (size_t)(cout0 + cl) * HW;
        float* o1 = o0 + HW;
#pragma unroll
        for (int mt = 0; mt < MTS; ++mt) {
            int mA = (mt0 + mt) * 16 + qr;
            int mB = mA + 8;
            int iA = (oh_base + mA / 56) * W + (mA % 56);
            int iB = (oh_base + mB / 56) * W + (mB % 56);
            o0[iA] = acc[mt][nn][0] + bq0;
            o1[iA] = acc[mt][nn][1] + bq1;
            o0[iB] = acc[mt][nn][2] + bq0;
            o1[iB] = acc[mt][nn][3] + bq1;
        }
    }
}

__global__ __launch_bounds__(256, 2)
void conv_mma_kernel(const float* __restrict__ in,
                     const float* __restrict__ biasp,
                     float* __restrict__ out)
{
    extern __shared__ uint32_t smem[];

    const int tid = threadIdx.x;
    const int w   = tid >> 5;
    const int wm  = w & 1;
    const int wn  = w >> 1;
    const int oh_base = blockIdx.x * 2;
    const int cout0   = blockIdx.y * 128;
    const int b       = blockIdx.z;

    const float* in_b  = in  + (size_t)b * C * HW;
    float*       out_b = out + (size_t)b * COUT * HW;

    if (wm == 0)
        conv_body<4, 0>(in_b, biasp, out_b, smem, oh_base, cout0, tid, wn, 0);
    else
        conv_body<3, 15>(in_b, biasp, out_b, smem, oh_base, cout0, tid, wn, 4);
}

extern "C" void kernel_launch(void* const* d_in, const int* in_sizes, int n_in,
                              void* d_out, int out_size)
{
    const float* in    = (const float*)d_in[0];
    const float* shift = (const float*)d_in[1];
    const float* sign  = (const float*)d_in[2];
    const float* bias  = (const float*)d_in[3];
    float* out = (float*)d_out;

    cudaFuncSetAttribute(conv_mma_kernel,
                         cudaFuncAttributeMaxDynamicSharedMemorySize, SMEM_BYTES);

    quant_weights_kernel<<<2304, 256>>>(shift, sign);
    dim3 grid(H / 2, COUT / 128, BATCH);               // 28 x 2 x 32
    conv_mma_kernel<<<grid, 256, SMEM_BYTES>>>(in, bias, out);
}

// round 16
// speedup vs baseline: 1.5781x; 1.2445x over previous
#include <cuda_runtime.h>
#include <cuda_fp16.h>
#include <math.h>
#include <stdint.h>

#define BATCH 32
#define C     256
#define COUT  256
#define H     56
#define W     56
#define HW    3136

#define XWORDS 1856          // live x words: 8 pair-planes x 4 rows x 58 cols (stride 232)
#define XPAD   2048
#define WWORDS 9216          // w buffer: 9 taps x (2 cb x 4 wn x 32 lanes x 32B swizzled)
#define SMEM_WORDS (2 * XPAD + 2 * WWORDS)      // 22528
#define SMEM_BYTES (SMEM_WORDS * 4)             // 90112

// Packed quantized fp16 weights, lane-major with 16B-chunk half-swap swizzle:
// [chunk(16)][tap(9)][cb(2)][wn(4)][64 x 16B chunks]
// Lane's 32B = chunks {(2*lane)^b, (2*lane+1)^b}, b=(lane>>2)&1.
__device__ unsigned short g_wq[16u * 9u * 256u * 16u];

// floor-to-2^-16-grid then round-to-fp16 (round_to_fixed clamps dead: |x|<<32768)
__device__ __forceinline__ uint32_t quant_pack(float a, float b) {
    float fa = (float)__float2int_rd(a * 65536.0f) * (1.0f / 65536.0f);
    float fb = (float)__float2int_rd(b * 65536.0f) * (1.0f / 65536.0f);
    __half2 h = __floats2half2_rn(fa, fb);
    return *(uint32_t*)&h;
}
__device__ __forceinline__ float quant_scalar(float x) {
    return (float)__float2int_rd(x * 65536.0f) * (1.0f / 65536.0f);
}

__device__ __forceinline__ uint32_t smem_u32(const void* p) {
    uint32_t a;
    asm("{ .reg .u64 t; cvta.to.shared.u64 t, %1; cvt.u32.u64 %0, t; }" : "=r"(a) : "l"(p));
    return a;
}
#define CP_ASYNC16(dst, src) \
    asm volatile("cp.async.cg.shared.global [%0], [%1], 16;" :: "r"(dst), "l"(src))
#define CP_COMMIT()  asm volatile("cp.async.commit_group;" ::: "memory")
#define CP_WAIT0()   asm volatile("cp.async.wait_group 0;" ::: "memory")

// ---------------- weight pre-quantization / packing ----------------
__global__ void quant_weights_kernel(const float* __restrict__ shiftp,
                                     const float* __restrict__ signp)
{
    int gid = blockIdx.x * blockDim.x + threadIdx.x;   // [cout][ci][tap]
    int cout = gid / (C * 9);
    int rem  = gid - cout * (C * 9);
    int ci   = rem / 9;
    int tap  = rem - ci * 9;

    float sr = rintf(fminf(fmaxf(shiftp[gid], -14.0f), 0.0f));
    float g  = rintf(signp[gid]);
    float sg = (g > 0.0f) ? 1.0f : ((g < 0.0f) ? -1.0f : 0.0f);
    float wf = ldexpf(sg, (int)sr);
    __half h = __float2half(wf);                       // exact

    int chunk = ci >> 4;
    int l     = ci & 15;
    int half  = l >> 3;            // k-half (ci +8)
    int qc    = (l & 7) >> 1;      // owner thread column
    int pos   = l & 1;             // low/high fp16 within word

    int cb = cout >> 7;            // 128-cout block (CTA)
    int r  = cout & 127;
    int wn = r >> 5;
    int nn = (r >> 3) & 3;
    int qr = r & 7;

    int lane  = qr * 4 + qc;
    int b     = (lane >> 2) & 1;                       // = qr & 1
    int cidx  = (2 * lane + (nn >> 1)) ^ b;            // 16B chunk index (0..63)
    int word  = cidx * 4 + (nn & 1) * 2 + half;        // word within region (0..255)
    size_t wd = ((size_t)(chunk * 9 + tap) * 2048) + cb * 1024 + wn * 256 + word;
    g_wq[wd * 2 + pos] = __half_as_ushort(h);
}

// ---------------- main MMA conv ----------------
// CTA: M=112 (2 rows), N=128. 8 warps = 2(M) x 4(N).
// MTS=4 warps: pure cp.async+MMA. MTS=3 warps (128 thr) own all x staging.
// x/w double-buffered, one barrier per chunk, unroll-2 for static smem addrs.
// B fragments: 2x LDS.128 per tap (conflict-free swizzle), replacing 4x LDS.64.

template<int MTS, int NS>
__device__ __forceinline__ void conv_body(
    const float* __restrict__ in_b,
    const float* __restrict__ biasp,
    float* __restrict__ out_b,
    uint32_t* __restrict__ smem,
    int oh_base, int cout0, int tid, int wn, int mt0)
{
    uint32_t* const sx0 = smem;
    uint32_t* const sx1 = smem + XPAD;
    uint32_t* const sw0 = smem + 2 * XPAD;
    uint32_t* const sw1 = smem + 2 * XPAD + WWORDS;
    const uint32_t sw0a = smem_u32(sw0), sw1a = smem_u32(sw1);

    const int lane = tid & 31;
    const int qc = lane & 3;
    const int qr = lane >> 2;
    const int bsw = (lane >> 2) & 1;
    const int wl0 = wn * 256 + (((2 * lane)     ^ bsw) << 2);  // word offsets
    const int wl1 = wn * 256 + (((2 * lane + 1) ^ bsw) << 2);

    int offA[MTS], offB[MTS];
#pragma unroll
    for (int mt = 0; mt < MTS; ++mt) {
        int mA = (mt0 + mt) * 16 + qr;
        int mB = mA + 8;
        offA[mt] = (mA / 56) * 58 + (mA % 56);
        offB[mt] = (mB / 56) * 58 + (mB % 56);
    }

    float acc[MTS][4][4];
#pragma unroll
    for (int mt = 0; mt < MTS; ++mt)
#pragma unroll
        for (int nn = 0; nn < 4; ++nn)
#pragma unroll
            for (int r = 0; r < 4; ++r) acc[mt][nn][r] = 0.0f;

    const int qc232 = qc * 232;
    const char* wsrc_base = (const char*)g_wq + ((size_t)cout0 * 32);

    // ---- staging geometry: NS slots per thread, stride 128 (wm=1 group only) ----
    int  xoff[NS > 0 ? NS : 1];
    bool xval[NS > 0 ? NS : 1];
    const int sbase = wn * 32 + lane;
    if (NS > 0) {
#pragma unroll
        for (int it = 0; it < NS; ++it) {
            int idx  = sbase + it * 128;
            int c    = idx / 232;
            int rem  = idx - c * 232;
            int row  = rem / 58;
            int col  = rem - row * 58;
            int ih   = oh_base + row - 1;
            int iw   = col - 1;
            xval[it] = (idx < XWORDS) && (ih >= 0) && (ih < H) && (iw >= 0) && (iw < W);
            xoff[it] = 2 * c * HW + ih * W + iw;
        }
#pragma unroll
        for (int it = 0; it < NS; ++it) {
            int idx = sbase + it * 128;
            if (idx < XWORDS) {
                float v0 = 0.0f, v1 = 0.0f;
                if (xval[it]) {
                    const float* p = in_b + xoff[it];
                    v0 = __ldg(p); v1 = __ldg(p + HW);
                }
                sx0[idx] = quant_pack(v0, v1);
            }
        }
    }
#pragma unroll
    for (int tap = 0; tap < 9; ++tap)
        CP_ASYNC16(sw0a + tap * 4096 + tid * 16,
                   wsrc_base + (size_t)tap * 8192 + tid * 16);
    CP_COMMIT();

#pragma unroll 2
    for (int chunk = 0; chunk < 16; ++chunk) {
        const int cur = chunk & 1;                 // compile-time after unroll-2
        uint32_t* const xc = cur ? sx1 : sx0;
        uint32_t* const xn = cur ? sx0 : sx1;
        const uint32_t* wc = cur ? sw1 : sw0;
        const uint32_t wna = cur ? sw0a : sw1a;
        const bool hasnext = (chunk < 15);

        CP_WAIT0();
        __syncthreads();   // cur buffers ready; nxt buffers free

        float pv0[NS > 0 ? NS : 1], pv1[NS > 0 ? NS : 1];
        if (NS > 0 && hasnext) {
            const float* inc_n = in_b + (size_t)(chunk + 1) * 16 * HW;
#pragma unroll
            for (int it = 0; it < NS; ++it) {
                pv0[it] = 0.0f; pv1[it] = 0.0f;
                if (xval[it]) {
                    const float* p = inc_n + xoff[it];
                    pv0[it] = __ldg(p); pv1[it] = __ldg(p + HW);
                }
            }
        }
        if (hasnext) {
            const char* wsrc = wsrc_base + (size_t)(chunk + 1) * 9 * 8192;
#pragma unroll
            for (int tap = 0; tap < 9; ++tap)
                CP_ASYNC16(wna + tap * 4096 + tid * 16,
                           wsrc + (size_t)tap * 8192 + tid * 16);
            CP_COMMIT();
        }

        // ---- pure MMA tap loop ----
#pragma unroll
        for (int tap = 0; tap < 9; ++tap) {
            const int kh = tap / 3, kw = tap - kh * 3;
            const int tadd = kh * 58 + kw;

            // 2x LDS.128: chunk0 = fragments nn0,nn1; chunk1 = nn2,nn3
            uint4 wA = *(const uint4*)&wc[tap * 1024 + wl0];
            uint4 wB = *(const uint4*)&wc[tap * 1024 + wl1];
            const uint32_t b0[4] = { wA.x, wA.z, wB.x, wB.z };
            const uint32_t b1[4] = { wA.y, wA.w, wB.y, wB.w };

#pragma unroll
            for (int mt = 0; mt < MTS; ++mt) {
                uint32_t a0 = xc[qc232 + tadd + offA[mt]];
                uint32_t a1 = xc[qc232 + tadd + offB[mt]];
                uint32_t a2 = xc[qc232 + 928 + tadd + offA[mt]];
                uint32_t a3 = xc[qc232 + 928 + tadd + offB[mt]];
#pragma unroll
                for (int nn = 0; nn < 4; ++nn) {
                    asm volatile(
                        "mma.sync.aligned.m16n8k16.row.col.f32.f16.f16.f32 "
                        "{%0,%1,%2,%3}, {%4,%5,%6,%7}, {%8,%9}, {%0,%1,%2,%3};\n"
                        : "+f"(acc[mt][nn][0]), "+f"(acc[mt][nn][1]),
                          "+f"(acc[mt][nn][2]), "+f"(acc[mt][nn][3])
                        : "r"(a0), "r"(a1), "r"(a2), "r"(a3),
                          "r"(b0[nn]), "r"(b1[nn]));
                }
            }
        }

        // STS next x — hazards covered by next top barrier
        if (NS > 0 && hasnext) {
#pragma unroll
            for (int it = 0; it < NS; ++it) {
                int idx = sbase + it * 128;
                if (idx < XWORDS)
                    xn[idx] = quant_pack(pv0[it], pv1[it]);
            }
        }
    }

    // ---- epilogue ----
#pragma unroll
    for (int nn = 0; nn < 4; ++nn) {
        int cl = wn * 32 + nn * 8 + 2 * qc;
        float bq0 = quant_scalar(biasp[cout0 + cl]);
        float bq1 = quant_scalar(biasp[cout0 + cl + 1]);
        float* o0 = out_b + (size_t)(cout0 + cl) * HW;
        float* o1 = o0 + HW;
#pragma unroll
        for (int mt = 0; mt < MTS; ++mt) {
            int mA = (mt0 + mt) * 16 + qr;
            int mB = mA + 8;
            int iA = (oh_base + mA / 56) * W + (mA % 56);
            int iB = (oh_base + mB / 56) * W + (mB % 56);
            o0[iA] = acc[mt][nn][0] + bq0;
            o1[iA] = acc[mt][nn][1] + bq1;
            o0[iB] = acc[mt][nn][2] + bq0;
            o1[iB] = acc[mt][nn][3] + bq1;
        }
    }
}

__global__ __launch_bounds__(256, 2)
void conv_mma_kernel(const float* __restrict__ in,
                     const float* __restrict__ biasp,
                     float* __restrict__ out)
{
    extern __shared__ uint32_t smem[];

    const int tid = threadIdx.x;
    const int w   = tid >> 5;
    const int wm  = w & 1;
    const int wn  = w >> 1;
    const int oh_base = blockIdx.x * 2;
    const int cout0   = blockIdx.y * 128;
    const int b       = blockIdx.z;

    const float* in_b  = in  + (size_t)b * C * HW;
    float*       out_b = out + (size_t)b * COUT * HW;

    if (wm == 0)
        conv_body<4, 0>(in_b, biasp, out_b, smem, oh_base, cout0, tid, wn, 0);
    else
        conv_body<3, 15>(in_b, biasp, out_b, smem, oh_base, cout0, tid, wn, 4);
}

extern "C" void kernel_launch(void* const* d_in, const int* in_sizes, int n_in,
                              void* d_out, int out_size)
{
    const float* in    = (const float*)d_in[0];
    const float* shift = (const float*)d_in[1];
    const float* sign  = (const float*)d_in[2];
    const float* bias  = (const float*)d_in[3];
    float* out = (float*)d_out;

    cudaFuncSetAttribute(conv_mma_kernel,
                         cudaFuncAttributeMaxDynamicSharedMemorySize, SMEM_BYTES);

    quant_weights_kernel<<<2304, 256>>>(shift, sign);
    dim3 grid(H / 2, COUT / 128, BATCH);               // 28 x 2 x 32
    conv_mma_kernel<<<grid, 256, SMEM_BYTES>>>(in, bias, out);
}